// round 14
// baseline (speedup 1.0000x reference)
// uniform_loss GB300 — R14: convert fused into tile_kernel (flag-based), reduce R13.
#include <cuda_runtime.h>
#include <cuda_fp8.h>
#include <cstdint>

#define N_PTS 16384
#define NBLK  128                       // number of 128-row blocks
#define NTILE 8256                      // NBLK*(NBLK+1)/2 upper-tri tiles
#define C1 20.609929155556625f          // log2(e)/T
#define C2 0.0805075357638931f          // C1/256  (compensates 16x quantization scale)
#define INV_T 14.285714285714286f

__device__ uint8_t g_X8[N_PTS * 128];             // e4m3 of 16*x, row-major 128 B/row
__device__ float   g_n2[N_PTS];                   // sum of q^2 per row (= MMA diagonal value)
__device__ float   g_part[(size_t)NBLK * N_PTS];  // [j-block][row] partial sums (transposed)
__device__ float   g_blk[NBLK];
__device__ int     g_cnt;
__device__ int     g_flag[NBLK];                  // block-converted flags (reset each run)

// ---------------------------------------------------------------- helpers
__device__ __forceinline__ uint32_t s2u(const void* p) {
    return (uint32_t)__cvta_generic_to_shared(p);
}
__device__ __forceinline__ void cp16(uint32_t s, const void* g) {
    asm volatile("cp.async.cg.shared.global [%0], [%1], 16;\n" :: "r"(s), "l"(g));
}
__device__ __forceinline__ float ex2(float x) {
    float r; asm("ex2.approx.f32 %0, %1;" : "=f"(r) : "f"(x)); return r;
}
__device__ __forceinline__ uint32_t sw(uint32_t b) {     // SW128 swizzle, 128B rows
    return b ^ ((b >> 3) & 0x70);
}
__device__ __forceinline__ void ldmx4(uint32_t (&r)[4], uint32_t addr) {
    asm volatile("ldmatrix.sync.aligned.m8n8.x4.shared.b16 {%0,%1,%2,%3}, [%4];\n"
                 : "=r"(r[0]), "=r"(r[1]), "=r"(r[2]), "=r"(r[3]) : "r"(addr));
}
__device__ __forceinline__ void qmma(float* c, const uint32_t* a, uint32_t b0, uint32_t b1) {
    asm volatile(
        "mma.sync.aligned.m16n8k32.row.col.f32.e4m3.e4m3.f32 "
        "{%0,%1,%2,%3}, {%4,%5,%6,%7}, {%8,%9}, {%0,%1,%2,%3};\n"
        : "+f"(c[0]), "+f"(c[1]), "+f"(c[2]), "+f"(c[3])
        : "r"(a[0]), "r"(a[1]), "r"(a[2]), "r"(a[3]), "r"(b0), "r"(b1));
}
__device__ __forceinline__ float fp8tof(uint32_t b) {
    __half_raw hr = __nv_cvt_fp8_to_halfraw((__nv_fp8_storage_t)b, __NV_E4M3);
    return __half2float(*(__half*)&hr);
}

// ---------------------------------------------------------------- one upper-tri tile per CTA
// CTAs 0..127 additionally convert block blockIdx.x (fp32 -> e4m3, + g_n2) first.
__global__ void __launch_bounds__(256, 2) tile_kernel(const float* __restrict__ x) {
    __shared__ uint8_t sA[16384];
    __shared__ uint8_t sB[16384];
    __shared__ float rowred[2][128];
    __shared__ float colred[4][128];

    const int tid  = threadIdx.x;
    const int lane = tid & 31;
    const int wid  = tid >> 5;
    const int wm   = wid & 3;     // 4 warps along M (32 rows each)
    const int wn   = wid >> 2;    // 2 warps along N (64 cols each)

    // ---- producer phase: first NBLK CTAs convert one block each
    if (blockIdx.x < NBLK) {
        const int b = blockIdx.x;
        const float* xb = x + (size_t)b * 128 * 128;
        // 8 warps x 16 rows, batched 4 rows for MLP; per-row math identical to
        // the old convert_kernel (lane = float4 index) -> g_X8/g_n2 bit-identical.
        for (int t = 0; t < 16; t += 4) {
            float4 v[4];
            #pragma unroll
            for (int k = 0; k < 4; k++) {
                int rr = wid * 16 + t + k;
                v[k] = ((const float4*)(xb + rr * 128))[lane];
            }
            #pragma unroll
            for (int k = 0; k < 4; k++) {
                int rr  = wid * 16 + t + k;
                int row = b * 128 + rr;
                uint32_t b0 = __nv_cvt_float_to_fp8(v[k].x * 16.f, __NV_SATFINITE, __NV_E4M3);
                uint32_t b1 = __nv_cvt_float_to_fp8(v[k].y * 16.f, __NV_SATFINITE, __NV_E4M3);
                uint32_t b2 = __nv_cvt_float_to_fp8(v[k].z * 16.f, __NV_SATFINITE, __NV_E4M3);
                uint32_t b3 = __nv_cvt_float_to_fp8(v[k].w * 16.f, __NV_SATFINITE, __NV_E4M3);
                ((uint32_t*)g_X8)[row * 32 + lane] =
                    b0 | (b1 << 8) | (b2 << 16) | (b3 << 24);
                float q0 = fp8tof(b0), q1 = fp8tof(b1), q2 = fp8tof(b2), q3 = fp8tof(b3);
                float n2 = q0 * q0 + q1 * q1 + q2 * q2 + q3 * q3;
                #pragma unroll
                for (int ofs = 16; ofs > 0; ofs >>= 1)
                    n2 += __shfl_xor_sync(0xffffffffu, n2, ofs);
                if (lane == 0) g_n2[row] = n2;
            }
        }
        __syncthreads();
        if (tid == 0) {
            __threadfence();                 // release: data before flag
            atomicExch(&g_flag[b], 1);
        }
    }

    // decode upper-tri tile index -> (I, J), J >= I
    int u = blockIdx.x;
    int I = (int)floorf(128.5f - sqrtf(128.5f * 128.5f - 2.0f * (float)u));
    if (I < 0) I = 0;
    if (I > 127) I = 127;
    #define OFS(i) ((i) * 128 - (i) * ((i) - 1) / 2)
    while (I < 127 && OFS(I + 1) <= u) I++;
    while (I > 0 && OFS(I) > u) I--;
    const int J = I + (u - OFS(I));
    #undef OFS

    // ---- wait until blocks I and J are converted (acquire)
    if (tid == 0) {
        while (atomicAdd(&g_flag[I], 0) == 0) __nanosleep(64);
        while (atomicAdd(&g_flag[J], 0) == 0) __nanosleep(64);
        __threadfence();
    }
    __syncthreads();

    // ---- load A (block I) and B (block J): 16 KB each, SW128 swizzled
    {
        const uint32_t dst = (tid < 128) ? s2u(sA) : s2u(sB);
        const uint8_t* src = &g_X8[(size_t)((tid < 128) ? I : J) * 128 * 128];
        const int ptid = tid & 127;
        #pragma unroll
        for (int i = 0; i < 8; i++) {
            int q = i * 128 + ptid;        // 0..1023 16B-chunks
            int row = q >> 3, c = q & 7;
            uint32_t b = (uint32_t)(row * 128 + c * 16);
            cp16(dst + sw(b), src + row * 128 + c * 16);
        }
    }
    asm volatile("cp.async.commit_group;\n" ::: "memory");
    asm volatile("cp.async.wait_group 0;\n" ::: "memory");
    __syncthreads();

    const uint32_t sAu = s2u(sA), sBu = s2u(sB);

    // per-thread running sums
    float rowl[2][2] = {{0.f, 0.f}, {0.f, 0.f}};
    float coll[8][2];
    #pragma unroll
    for (int nb = 0; nb < 8; nb++) { coll[nb][0] = 0.f; coll[nb][1] = 0.f; }

    // ---- software-pipelined quarters: 32x16 each, double-buffered accs.
    float acc[2][2][2][4];   // [buf][mf][nbq][4]

    #define MMA_QUARTER(qq, buf) do {                                               \
        _Pragma("unroll")                                                           \
        for (int mf = 0; mf < 2; mf++)                                              \
            _Pragma("unroll")                                                       \
            for (int nq = 0; nq < 2; nq++)                                          \
                _Pragma("unroll")                                                   \
                for (int e = 0; e < 4; e++) acc[buf][mf][nq][e] = 0.f;              \
        _Pragma("unroll")                                                           \
        for (int kk = 0; kk < 4; kk++) {                                            \
            const int ab = kk * 32 + ((lane >> 4) << 4);                            \
            uint32_t a0[4], a1[4], r4[4];                                           \
            ldmx4(a0, sAu + sw((uint32_t)((wm * 32 + (lane & 15)) * 128 + ab)));    \
            ldmx4(a1, sAu + sw((uint32_t)((wm * 32 + 16 + (lane & 15)) * 128 + ab)));\
            ldmx4(r4, sBu + sw((uint32_t)((wn * 64 + (qq) * 16 + (lane & 15)) * 128 + ab)));\
            qmma(acc[buf][0][0], a0, r4[0], r4[2]);                                 \
            qmma(acc[buf][0][1], a0, r4[1], r4[3]);                                 \
            qmma(acc[buf][1][0], a1, r4[0], r4[2]);                                 \
            qmma(acc[buf][1][1], a1, r4[1], r4[3]);                                 \
        }                                                                           \
    } while (0)

    #define EPILOGUE(qq, buf) do {                                                  \
        _Pragma("unroll")                                                           \
        for (int mf = 0; mf < 2; mf++)                                              \
            _Pragma("unroll")                                                       \
            for (int nq = 0; nq < 2; nq++) {                                        \
                const int nb = (qq) * 2 + nq;                                       \
                float e0 = ex2(fmaf(acc[buf][mf][nq][0], C2, -C1));                 \
                float e1 = ex2(fmaf(acc[buf][mf][nq][1], C2, -C1));                 \
                float e2 = ex2(fmaf(acc[buf][mf][nq][2], C2, -C1));                 \
                float e3 = ex2(fmaf(acc[buf][mf][nq][3], C2, -C1));                 \
                rowl[mf][0] += e0 + e1;                                             \
                rowl[mf][1] += e2 + e3;                                             \
                coll[nb][0] += e0 + e2;                                             \
                coll[nb][1] += e1 + e3;                                             \
            }                                                                       \
    } while (0)

    MMA_QUARTER(0, 0);
    MMA_QUARTER(1, 1);
    EPILOGUE(0, 0);
    MMA_QUARTER(2, 0);
    EPILOGUE(1, 1);
    MMA_QUARTER(3, 1);
    EPILOGUE(2, 0);
    EPILOGUE(3, 1);

    #undef MMA_QUARTER
    #undef EPILOGUE

    // row reduce: sum over the 4 lanes of each quad (cols)
    #pragma unroll
    for (int mf = 0; mf < 2; mf++)
        #pragma unroll
        for (int h = 0; h < 2; h++) {
            float v = rowl[mf][h];
            v += __shfl_xor_sync(0xffffffffu, v, 1);
            v += __shfl_xor_sync(0xffffffffu, v, 2);
            if ((lane & 3) == 0)
                rowred[wn][wm * 32 + mf * 16 + h * 8 + (lane >> 2)] = v;
        }
    // col reduce: sum over the 8 row-groups (lane>>2)
    #pragma unroll
    for (int nb = 0; nb < 8; nb++)
        #pragma unroll
        for (int h = 0; h < 2; h++) {
            float v = coll[nb][h];
            v += __shfl_xor_sync(0xffffffffu, v, 4);
            v += __shfl_xor_sync(0xffffffffu, v, 8);
            v += __shfl_xor_sync(0xffffffffu, v, 16);
            if (lane < 4)
                colred[wm][wn * 64 + nb * 8 + 2 * lane + h] = v;
        }
    __syncthreads();

    // transposed layout: slot j of row i lives at g_part[j*N_PTS + i] -> coalesced
    if (tid < 128) {
        float rs = rowred[0][tid] + rowred[1][tid];
        g_part[(size_t)J * N_PTS + I * 128 + tid] = rs;
        if (I != J) {
            float cs = (colred[0][tid] + colred[1][tid])
                     + (colred[2][tid] + colred[3][tid]);
            g_part[(size_t)I * N_PTS + J * 128 + tid] = cs;
        }
    }
}

// ---------------------------------------------------------------- fused reduce + final
// 256 threads/block: thread t sums j-half (t>>7) for row (blk*128 + (t&127)).
__global__ void reduce_kernel(float* __restrict__ out) {
    __shared__ float half_s[2][128];
    __shared__ float red[128];
    __shared__ int lastflag;
    const int rl   = threadIdx.x & 127;
    const int half = threadIdx.x >> 7;
    const int i = blockIdx.x * 128 + rl;
    float s = 0.f;
    #pragma unroll 8
    for (int j = half * 64; j < half * 64 + 64; j++)
        s += g_part[(size_t)j * N_PTS + i];      // coalesced across the warp
    half_s[half][rl] = s;
    __syncthreads();
    if (threadIdx.x < 128) {
        float t = half_s[0][rl] + half_s[1][rl];
        // replace quantized diagonal term with the exact exp(0)=1
        t += 1.0f - ex2(fmaf(g_n2[i], C2, -C1));
        red[rl] = __logf(t);
    }
    __syncthreads();
    for (int ofs = 64; ofs > 0; ofs >>= 1) {
        if (threadIdx.x < ofs) red[threadIdx.x] += red[threadIdx.x + ofs];
        __syncthreads();
    }
    if (threadIdx.x == 0) {
        g_blk[blockIdx.x] = red[0];
        __threadfence();
        lastflag = (atomicAdd(&g_cnt, 1) == NBLK - 1);
    }
    __syncthreads();
    if (lastflag && threadIdx.x >= 128)
        g_flag[threadIdx.x - 128] = 0;           // reset converter flags for replay
    if (lastflag && threadIdx.x < 128) {
        red[threadIdx.x] = g_blk[threadIdx.x];
        __syncthreads();
        for (int ofs = 64; ofs > 0; ofs >>= 1) {
            if (threadIdx.x < ofs) red[threadIdx.x] += red[threadIdx.x + ofs];
            __syncthreads();
        }
        if (threadIdx.x == 0) {
            out[0] = red[0] / (float)N_PTS + INV_T;
            g_cnt = 0;                            // reset for graph replay
        }
    }
}

// ---------------------------------------------------------------- launch
extern "C" void kernel_launch(void* const* d_in, const int* in_sizes, int n_in,
                              void* d_out, int out_size) {
    const float* x = (const float*)d_in[0];
    float* out = (float*)d_out;
    tile_kernel<<<NTILE, 256>>>(x);
    reduce_kernel<<<NBLK, 256>>>(out);
}

// round 15
// speedup vs baseline: 1.1445x; 1.1445x over previous
// uniform_loss GB300 — R15: R13 tile kernel verbatim; reduce grid=512 (latency fix);
// convert 4 rows/warp. R14 fusion reverted.
#include <cuda_runtime.h>
#include <cuda_fp8.h>
#include <cstdint>

#define N_PTS 16384
#define NBLK  128                       // number of 128-row blocks
#define NTILE 8256                      // NBLK*(NBLK+1)/2 upper-tri tiles
#define NRED  512                       // reduce blocks (32 rows each)
#define C1 20.609929155556625f          // log2(e)/T
#define C2 0.0805075357638931f          // C1/256  (compensates 16x quantization scale)
#define INV_T 14.285714285714286f

__device__ uint8_t g_X8[N_PTS * 128];             // e4m3 of 16*x, row-major 128 B/row
__device__ float   g_n2[N_PTS];                   // sum of q^2 per row (= MMA diagonal value)
__device__ float   g_part[(size_t)NBLK * N_PTS];  // [j-block][row] partial sums (transposed)
__device__ float   g_blk2[NRED];
__device__ int     g_cnt;

// ---------------------------------------------------------------- helpers
__device__ __forceinline__ uint32_t s2u(const void* p) {
    return (uint32_t)__cvta_generic_to_shared(p);
}
__device__ __forceinline__ void cp16(uint32_t s, const void* g) {
    asm volatile("cp.async.cg.shared.global [%0], [%1], 16;\n" :: "r"(s), "l"(g));
}
__device__ __forceinline__ float ex2(float x) {
    float r; asm("ex2.approx.f32 %0, %1;" : "=f"(r) : "f"(x)); return r;
}
__device__ __forceinline__ uint32_t sw(uint32_t b) {     // SW128 swizzle, 128B rows
    return b ^ ((b >> 3) & 0x70);
}
__device__ __forceinline__ void ldmx4(uint32_t (&r)[4], uint32_t addr) {
    asm volatile("ldmatrix.sync.aligned.m8n8.x4.shared.b16 {%0,%1,%2,%3}, [%4];\n"
                 : "=r"(r[0]), "=r"(r[1]), "=r"(r[2]), "=r"(r[3]) : "r"(addr));
}
__device__ __forceinline__ void qmma(float* c, const uint32_t* a, uint32_t b0, uint32_t b1) {
    asm volatile(
        "mma.sync.aligned.m16n8k32.row.col.f32.e4m3.e4m3.f32 "
        "{%0,%1,%2,%3}, {%4,%5,%6,%7}, {%8,%9}, {%0,%1,%2,%3};\n"
        : "+f"(c[0]), "+f"(c[1]), "+f"(c[2]), "+f"(c[3])
        : "r"(a[0]), "r"(a[1]), "r"(a[2]), "r"(a[3]), "r"(b0), "r"(b1));
}
__device__ __forceinline__ float fp8tof(uint32_t b) {
    __half_raw hr = __nv_cvt_fp8_to_halfraw((__nv_fp8_storage_t)b, __NV_E4M3);
    return __half2float(*(__half*)&hr);
}

// ---------------------------------------------------------------- convert: fp32 -> e4m3(16x), + row n2
// Four rows per warp; all loads batched first (MLP=4), then convert + 4 shuffle trees.
__global__ void convert_kernel(const float* __restrict__ x) {
    int w    = (blockIdx.x * blockDim.x + threadIdx.x) >> 5;  // warp id, 0..4095
    int lane = threadIdx.x & 31;
    if (w >= N_PTS / 4) return;
    const int r0 = w * 4;

    float4 v[4];
    #pragma unroll
    for (int k = 0; k < 4; k++)
        v[k] = ((const float4*)(x + (r0 + k) * 128))[lane];

    float n2[4];
    #pragma unroll
    for (int k = 0; k < 4; k++) {
        uint32_t b0 = __nv_cvt_float_to_fp8(v[k].x * 16.f, __NV_SATFINITE, __NV_E4M3);
        uint32_t b1 = __nv_cvt_float_to_fp8(v[k].y * 16.f, __NV_SATFINITE, __NV_E4M3);
        uint32_t b2 = __nv_cvt_float_to_fp8(v[k].z * 16.f, __NV_SATFINITE, __NV_E4M3);
        uint32_t b3 = __nv_cvt_float_to_fp8(v[k].w * 16.f, __NV_SATFINITE, __NV_E4M3);
        ((uint32_t*)g_X8)[(r0 + k) * 32 + lane] = b0 | (b1 << 8) | (b2 << 16) | (b3 << 24);
        float q0 = fp8tof(b0), q1 = fp8tof(b1), q2 = fp8tof(b2), q3 = fp8tof(b3);
        n2[k] = q0 * q0 + q1 * q1 + q2 * q2 + q3 * q3;
    }
    #pragma unroll
    for (int ofs = 16; ofs > 0; ofs >>= 1) {
        #pragma unroll
        for (int k = 0; k < 4; k++)
            n2[k] += __shfl_xor_sync(0xffffffffu, n2[k], ofs);
    }
    if (lane == 0) {
        #pragma unroll
        for (int k = 0; k < 4; k++) g_n2[r0 + k] = n2[k];
    }
}

// ---------------------------------------------------------------- one upper-tri tile per CTA
__global__ void __launch_bounds__(256, 2) tile_kernel() {
    __shared__ uint8_t sA[16384];
    __shared__ uint8_t sB[16384];
    __shared__ float rowred[2][128];
    __shared__ float colred[4][128];

    const int tid  = threadIdx.x;
    const int lane = tid & 31;
    const int wid  = tid >> 5;
    const int wm   = wid & 3;     // 4 warps along M (32 rows each)
    const int wn   = wid >> 2;    // 2 warps along N (64 cols each)

    // decode upper-tri tile index -> (I, J), J >= I
    int u = blockIdx.x;
    int I = (int)floorf(128.5f - sqrtf(128.5f * 128.5f - 2.0f * (float)u));
    if (I < 0) I = 0;
    if (I > 127) I = 127;
    #define OFS(i) ((i) * 128 - (i) * ((i) - 1) / 2)
    while (I < 127 && OFS(I + 1) <= u) I++;
    while (I > 0 && OFS(I) > u) I--;
    const int J = I + (u - OFS(I));
    #undef OFS

    // ---- load A (block I) and B (block J): 16 KB each, SW128 swizzled
    {
        const uint32_t dst = (tid < 128) ? s2u(sA) : s2u(sB);
        const uint8_t* src = &g_X8[(size_t)((tid < 128) ? I : J) * 128 * 128];
        const int ptid = tid & 127;
        #pragma unroll
        for (int i = 0; i < 8; i++) {
            int q = i * 128 + ptid;        // 0..1023 16B-chunks
            int row = q >> 3, c = q & 7;
            uint32_t b = (uint32_t)(row * 128 + c * 16);
            cp16(dst + sw(b), src + row * 128 + c * 16);
        }
    }
    asm volatile("cp.async.commit_group;\n" ::: "memory");
    asm volatile("cp.async.wait_group 0;\n" ::: "memory");
    __syncthreads();

    const uint32_t sAu = s2u(sA), sBu = s2u(sB);

    // per-thread running sums
    float rowl[2][2] = {{0.f, 0.f}, {0.f, 0.f}};
    float coll[8][2];
    #pragma unroll
    for (int nb = 0; nb < 8; nb++) { coll[nb][0] = 0.f; coll[nb][1] = 0.f; }

    // ---- software-pipelined quarters: 32x16 each, double-buffered accs.
    float acc[2][2][2][4];   // [buf][mf][nbq][4]

    #define MMA_QUARTER(qq, buf) do {                                               \
        _Pragma("unroll")                                                           \
        for (int mf = 0; mf < 2; mf++)                                              \
            _Pragma("unroll")                                                       \
            for (int nq = 0; nq < 2; nq++)                                          \
                _Pragma("unroll")                                                   \
                for (int e = 0; e < 4; e++) acc[buf][mf][nq][e] = 0.f;              \
        _Pragma("unroll")                                                           \
        for (int kk = 0; kk < 4; kk++) {                                            \
            const int ab = kk * 32 + ((lane >> 4) << 4);                            \
            uint32_t a0[4], a1[4], r4[4];                                           \
            ldmx4(a0, sAu + sw((uint32_t)((wm * 32 + (lane & 15)) * 128 + ab)));    \
            ldmx4(a1, sAu + sw((uint32_t)((wm * 32 + 16 + (lane & 15)) * 128 + ab)));\
            ldmx4(r4, sBu + sw((uint32_t)((wn * 64 + (qq) * 16 + (lane & 15)) * 128 + ab)));\
            qmma(acc[buf][0][0], a0, r4[0], r4[2]);                                 \
            qmma(acc[buf][0][1], a0, r4[1], r4[3]);                                 \
            qmma(acc[buf][1][0], a1, r4[0], r4[2]);                                 \
            qmma(acc[buf][1][1], a1, r4[1], r4[3]);                                 \
        }                                                                           \
    } while (0)

    #define EPILOGUE(qq, buf) do {                                                  \
        _Pragma("unroll")                                                           \
        for (int mf = 0; mf < 2; mf++)                                              \
            _Pragma("unroll")                                                       \
            for (int nq = 0; nq < 2; nq++) {                                        \
                const int nb = (qq) * 2 + nq;                                       \
                float e0 = ex2(fmaf(acc[buf][mf][nq][0], C2, -C1));                 \
                float e1 = ex2(fmaf(acc[buf][mf][nq][1], C2, -C1));                 \
                float e2 = ex2(fmaf(acc[buf][mf][nq][2], C2, -C1));                 \
                float e3 = ex2(fmaf(acc[buf][mf][nq][3], C2, -C1));                 \
                rowl[mf][0] += e0 + e1;                                             \
                rowl[mf][1] += e2 + e3;                                             \
                coll[nb][0] += e0 + e2;                                             \
                coll[nb][1] += e1 + e3;                                             \
            }                                                                       \
    } while (0)

    MMA_QUARTER(0, 0);
    MMA_QUARTER(1, 1);
    EPILOGUE(0, 0);
    MMA_QUARTER(2, 0);
    EPILOGUE(1, 1);
    MMA_QUARTER(3, 1);
    EPILOGUE(2, 0);
    EPILOGUE(3, 1);

    #undef MMA_QUARTER
    #undef EPILOGUE

    // row reduce: sum over the 4 lanes of each quad (cols)
    #pragma unroll
    for (int mf = 0; mf < 2; mf++)
        #pragma unroll
        for (int h = 0; h < 2; h++) {
            float v = rowl[mf][h];
            v += __shfl_xor_sync(0xffffffffu, v, 1);
            v += __shfl_xor_sync(0xffffffffu, v, 2);
            if ((lane & 3) == 0)
                rowred[wn][wm * 32 + mf * 16 + h * 8 + (lane >> 2)] = v;
        }
    // col reduce: sum over the 8 row-groups (lane>>2)
    #pragma unroll
    for (int nb = 0; nb < 8; nb++)
        #pragma unroll
        for (int h = 0; h < 2; h++) {
            float v = coll[nb][h];
            v += __shfl_xor_sync(0xffffffffu, v, 4);
            v += __shfl_xor_sync(0xffffffffu, v, 8);
            v += __shfl_xor_sync(0xffffffffu, v, 16);
            if (lane < 4)
                colred[wm][wn * 64 + nb * 8 + 2 * lane + h] = v;
        }
    __syncthreads();

    // transposed layout: slot j of row i lives at g_part[j*N_PTS + i] -> coalesced
    if (tid < 128) {
        float rs = rowred[0][tid] + rowred[1][tid];
        g_part[(size_t)J * N_PTS + I * 128 + tid] = rs;
        if (I != J) {
            float cs = (colred[0][tid] + colred[1][tid])
                     + (colred[2][tid] + colred[3][tid]);
            g_part[(size_t)I * N_PTS + J * 128 + tid] = cs;
        }
    }
}

// ---------------------------------------------------------------- fused reduce + final
// 512 blocks x 256 threads; block owns 32 rows. Warp sg sums j in [16*sg, 16*sg+16)
// for 32 consecutive rows (coalesced). Deterministic fixed-order combines throughout.
__global__ void reduce_kernel(float* __restrict__ out) {
    __shared__ float seg[8][32];
    __shared__ float red[128];
    __shared__ int lastflag;
    const int r  = threadIdx.x & 31;     // row within block
    const int sg = threadIdx.x >> 5;     // j-segment 0..7
    const int i  = blockIdx.x * 32 + r;

    float s = 0.f;
    #pragma unroll
    for (int j = sg * 16; j < sg * 16 + 16; j++)
        s += g_part[(size_t)j * N_PTS + i];
    seg[sg][r] = s;
    __syncthreads();

    if (threadIdx.x < 32) {
        float t = ((seg[0][r] + seg[1][r]) + (seg[2][r] + seg[3][r]))
                + ((seg[4][r] + seg[5][r]) + (seg[6][r] + seg[7][r]));
        t += 1.0f - ex2(fmaf(g_n2[i], C2, -C1));   // exact diagonal
        float lg = __logf(t);
        #pragma unroll
        for (int ofs = 16; ofs > 0; ofs >>= 1)
            lg += __shfl_xor_sync(0xffffffffu, lg, ofs);
        if (r == 0) {
            g_blk2[blockIdx.x] = lg;
            __threadfence();
            lastflag = (atomicAdd(&g_cnt, 1) == NRED - 1);
        }
    }
    __syncthreads();

    if (lastflag) {
        if (threadIdx.x < 128) {
            float v = ((g_blk2[threadIdx.x] + g_blk2[threadIdx.x + 128])
                     + (g_blk2[threadIdx.x + 256] + g_blk2[threadIdx.x + 384]));
            red[threadIdx.x] = v;
        }
        __syncthreads();
        for (int ofs = 64; ofs > 0; ofs >>= 1) {
            if (threadIdx.x < ofs) red[threadIdx.x] += red[threadIdx.x + ofs];
            __syncthreads();
        }
        if (threadIdx.x == 0) {
            out[0] = red[0] / (float)N_PTS + INV_T;
            g_cnt = 0;                            // reset for graph replay
        }
    }
}

// ---------------------------------------------------------------- launch
extern "C" void kernel_launch(void* const* d_in, const int* in_sizes, int n_in,
                              void* d_out, int out_size) {
    const float* x = (const float*)d_in[0];
    float* out = (float*)d_out;
    convert_kernel<<<(N_PTS / 4 * 32 + 255) / 256, 256>>>(x);
    tile_kernel<<<NTILE, 256>>>();
    reduce_kernel<<<NRED, 256>>>(out);
}